// round 10
// baseline (speedup 1.0000x reference)
#include <cuda_runtime.h>
#include <cuda_fp16.h>
#include <cstdint>

// ---------------- problem constants ----------------
#define BB    8
#define CINC  128
#define COUT  128
#define HH    64
#define WW    64
#define HW    4096
#define KK    9
#define NPHASE 18      // K = 1152 = 18 phases of 64 (phase c -> tap c>>1, cin half c&1)
#define NPIX  64       // pixels per CTA (1 output row)
#define KPADH 72       // padded row length in halves (144B rows, 16B aligned, LDSM conflict-free)

// ---------------- dynamic smem layout (bytes) ----------------
#define OFF_IDX  0                         // ushort4[9*64] = 4608
#define OFF_WGT  4608                      // float4[9*64]  = 9216 -> 13824
#define VTILE_BYTES (NPIX * KPADH * 2)     // 9216
#define OFF_V0   13824
#define OFF_V1   (OFF_V0 + VTILE_BYTES)    // 23040
#define SMEM_TOTAL (OFF_V1 + VTILE_BYTES)  // 32256

// weights pre-permuted into m16n8k16 fp16 A-fragment order:
// g_wfh[(kstep16_global*8 + mblock)*32 + lane] = uint4{a0,a1,a2,a3} (each a half2)
__device__ uint4 g_wfh[72 * 8 * 32];
// NHWC-tiled x in fp16: g_xh[b][cinhalf(2)][yx][cin64]  (8 MB)
// -> the 64 cin of one phase are one contiguous, 128B-aligned cache line per pixel
__device__ __half g_xh[BB * 2 * HW * 64];

__device__ __forceinline__ void mma_f16(float* d, const uint4 a, uint32_t b0, uint32_t b1) {
    asm volatile(
        "mma.sync.aligned.m16n8k16.row.col.f32.f16.f16.f32 "
        "{%0,%1,%2,%3}, {%4,%5,%6,%7}, {%8,%9}, {%0,%1,%2,%3};"
        : "+f"(d[0]), "+f"(d[1]), "+f"(d[2]), "+f"(d[3])
        : "r"(a.x), "r"(a.y), "r"(a.z), "r"(a.w), "r"(b0), "r"(b1));
}

__device__ __forceinline__ uint32_t smem_u32(const void* p) {
    uint32_t a;
    asm("{ .reg .u64 t; cvta.to.shared.u64 t, %1; cvt.u32.u64 %0, t; }" : "=r"(a) : "l"(p));
    return a;
}

// ---------------- merged prep: x transpose (blocks 0..2047) + weight permute (2048..2119) ----
__global__ void prep_all_kernel(const float* __restrict__ x,
                                const float* __restrict__ weight) {
    __shared__ float ts[32][65];
    const int bid = blockIdx.x;
    const int tid = threadIdx.x;

    if (bid < 2048) {
        // x transpose: NCHW f32 -> [b][cinhalf][yx][cin64] fp16
        const int yxt = bid & 63;
        const int blk = (bid >> 6) & 3;        // cin32 block 0..3
        const int b   = bid >> 8;
        const int yx0 = yxt * 64;

        const int yxl = tid & 63, cl = tid >> 6;
        const float* src = x + (((size_t)(b * CINC + blk * 32)) << 12) + yx0 + yxl;
        #pragma unroll
        for (int i = 0; i < 8; i++) {
            const int c = cl + i * 4;
            ts[c][yxl] = src[(size_t)c << 12];
        }
        __syncthreads();

        __half* dst = g_xh + ((((size_t)(b * 2 + (blk >> 1)) << 12) + yx0) << 6)
                    + ((blk & 1) << 5);
        const int c2 = tid & 31, yq = tid >> 5;
        #pragma unroll
        for (int i = 0; i < 8; i++) {
            const int yx = yq + i * 8;
            dst[(size_t)yx * 64 + c2] = __float2half(ts[c2][yx]);
        }
    } else {
        // weight prep: fp16 round + A-fragment permutation (18432 fragments)
        const int t = (bid - 2048) * 256 + tid;
        const int lane = t & 31;
        const int mb   = (t >> 5) & 7;
        const int ks   = (t >> 8) & 1;
        const int c    = t >> 9;                     // 32-k chunk id 0..35
        const int grp = lane >> 2, t4 = lane & 3;
        const int tap = c >> 2;
        const int cb  = ((c & 3) << 5) + ks * 16;    // cin base of this k16 step
        const int kA  = cb + t4 * 2;
        const int kB  = kA + 8;
        const int co0 = mb * 16 + grp;
        const int co1 = co0 + 8;
        #define WF(co, cin) __float2half_rn(weight[((co) * CINC + (cin)) * KK + tap])
        __half2 a0 = __halves2half2(WF(co0, kA), WF(co0, kA + 1));
        __half2 a1 = __halves2half2(WF(co1, kA), WF(co1, kA + 1));
        __half2 a2 = __halves2half2(WF(co0, kB), WF(co0, kB + 1));
        __half2 a3 = __halves2half2(WF(co1, kB), WF(co1, kB + 1));
        #undef WF
        uint4 u;
        u.x = *(uint32_t*)&a0; u.y = *(uint32_t*)&a1;
        u.z = *(uint32_t*)&a2; u.w = *(uint32_t*)&a3;
        g_wfh[t] = u;   // t == (kstep16_global*8 + mb)*32 + lane by construction
    }
}

// ---------------- main kernel ----------------
__global__ __launch_bounds__(256, 2)
void deform_conv_mma_kernel(const float* __restrict__ offs,
                            const float* __restrict__ bias,
                            float* __restrict__ out)
{
    extern __shared__ char smem[];
    ushort4* sIdx = (ushort4*)(smem + OFF_IDX);
    float4*  sWgt = (float4*)(smem + OFF_WGT);
    const uint32_t sb = smem_u32(smem);

    const int tid  = threadIdx.x;
    const int wid  = tid >> 5;
    const int lane = tid & 31;

    const int b  = blockIdx.x >> 6;       // 64 CTAs per image (1 row each)
    const int ho = blockIdx.x & 63;       // output row

    // ---- 1. sampling tables: 9 taps x 64 pix ----
    for (int e = tid; e < KK * NPIX; e += 256) {
        const int t  = e >> 6;
        const int wo = e & 63;
        const int kh = t / 3;
        const int kw = t - kh * 3;
        const float* ob = offs + (((size_t)b * (2 * KK) + 2 * t) * HH + ho) * WW + wo;
        const float dy = ob[0];
        const float dx = ob[HW];
        const float py = (float)(ho - 1 + kh) + dy;
        const float px = (float)(wo - 1 + kw) + dx;
        const float y0f = floorf(py), x0f = floorf(px);
        const float ly = py - y0f, lx = px - x0f;
        const int y0 = (int)y0f, x0 = (int)x0f;
        const float wy0 = (y0 >= 0     && y0 < HH)     ? (1.0f - ly) : 0.0f;
        const float wy1 = (y0 + 1 >= 0 && y0 + 1 < HH) ? ly          : 0.0f;
        const float wx0 = (x0 >= 0     && x0 < WW)     ? (1.0f - lx) : 0.0f;
        const float wx1 = (x0 + 1 >= 0 && x0 + 1 < WW) ? lx          : 0.0f;
        const int cy0 = min(max(y0, 0), HH - 1), cy1 = min(max(y0 + 1, 0), HH - 1);
        const int cx0 = min(max(x0, 0), WW - 1), cx1 = min(max(x0 + 1, 0), WW - 1);
        sIdx[e] = make_ushort4((unsigned short)(cy0 * WW + cx0),
                               (unsigned short)(cy0 * WW + cx1),
                               (unsigned short)(cy1 * WW + cx0),
                               (unsigned short)(cy1 * WW + cx1));
        sWgt[e] = make_float4(wy0 * wx0, wy0 * wx1, wy1 * wx0, wy1 * wx1);
    }
    __syncthreads();

    // ---- 2. GEMM setup ----
    const int pixg  = tid >> 3;           // pixel group 0..31
    const int lane8 = tid & 7;            // cin octet within 64 (8 halves = 16B)
    const int grp   = lane >> 2;
    const int t4    = lane & 3;

    // ldmatrix lane address components
    const int lm_pix = (lane & 7) + ((lane >> 4) << 3);  // 0..15
    const int lm_k   = ((lane >> 3) & 1) * 8;            // 0 or 8

    float acc[8][4];
    #pragma unroll
    for (int nt = 0; nt < 8; nt++)
        #pragma unroll
        for (int q = 0; q < 4; q++) acc[nt][q] = 0.0f;

    // corner prefetch registers: [pass][corner]
    uint4 pre[2][4];

    // issue gather LDGs for phase c into pre[][]
    auto issue_gather = [&](int c) {
        const int tap     = c >> 1;
        const int cinhalf = c & 1;
        const __half* pl = g_xh + ((size_t)(b * 2 + cinhalf) << 18);
        #pragma unroll
        for (int pass = 0; pass < 2; pass++) {
            const int pix = pass * 32 + pixg;
            const ushort4 q = sIdx[tap * 64 + pix];
            pre[pass][0] = __ldg((const uint4*)(pl + (size_t)q.x * 64) + lane8);
            pre[pass][1] = __ldg((const uint4*)(pl + (size_t)q.y * 64) + lane8);
            pre[pass][2] = __ldg((const uint4*)(pl + (size_t)q.z * 64) + lane8);
            pre[pass][3] = __ldg((const uint4*)(pl + (size_t)q.w * 64) + lane8);
        }
    };

    // blend prefetched corners (fp32) and store fp16 to the v tile of phase c
    auto blend_store = [&](int c) {
        const int tap = c >> 1;
        char* vb = smem + OFF_V0 + (c & 1) * VTILE_BYTES;
        #pragma unroll
        for (int pass = 0; pass < 2; pass++) {
            const int pix = pass * 32 + pixg;
            const float4 w = sWgt[tap * 64 + pix];
            const uint32_t* p0 = (const uint32_t*)&pre[pass][0];
            const uint32_t* p1 = (const uint32_t*)&pre[pass][1];
            const uint32_t* p2 = (const uint32_t*)&pre[pass][2];
            const uint32_t* p3 = (const uint32_t*)&pre[pass][3];
            uint4 st;
            uint32_t* s = (uint32_t*)&st;
            #pragma unroll
            for (int j = 0; j < 4; j++) {
                const float2 f0 = __half22float2(*(const __half2*)&p0[j]);
                const float2 f1 = __half22float2(*(const __half2*)&p1[j]);
                const float2 f2 = __half22float2(*(const __half2*)&p2[j]);
                const float2 f3 = __half22float2(*(const __half2*)&p3[j]);
                float2 r;
                r.x = w.x * f0.x + w.y * f1.x + w.z * f2.x + w.w * f3.x;
                r.y = w.x * f0.y + w.y * f1.y + w.z * f2.y + w.w * f3.y;
                const __half2 h = __float22half2_rn(r);
                s[j] = *(const uint32_t*)&h;
            }
            *(uint4*)(vb + pix * (KPADH * 2) + lane8 * 16) = st;
        }
    };

    // ---- 3. pipelined phase loop: LDG(c+1) -> mma(c) -> blend/STS(c+1) -> sync ----
    issue_gather(0);
    blend_store(0);
    __syncthreads();

    for (int c = 0; c < NPHASE; c++) {
        const uint32_t vb32 = sb + OFF_V0 + (c & 1) * VTILE_BYTES;

        if (c + 1 < NPHASE) issue_gather(c + 1);

        // mma: this warp = m-block wid (16 co) x 64 pix; 4 ksteps of k16
        #pragma unroll
        for (int ks = 0; ks < 4; ks++) {
            const int g = (c << 2) + ks;     // global k16 step 0..71
            const uint4 A = __ldg(&g_wfh[(g * 8 + wid) * 32 + lane]);
            #pragma unroll
            for (int p = 0; p < 4; p++) {
                const uint32_t addr = vb32
                    + (uint32_t)(p * 16 + lm_pix) * (KPADH * 2)
                    + (uint32_t)(ks * 16 + lm_k) * 2;
                uint32_t r0, r1, r2, r3;
                asm volatile(
                    "ldmatrix.sync.aligned.m8n8.x4.shared.b16 {%0,%1,%2,%3}, [%4];"
                    : "=r"(r0), "=r"(r1), "=r"(r2), "=r"(r3) : "r"(addr));
                mma_f16(acc[p * 2],     A, r0, r1);
                mma_f16(acc[p * 2 + 1], A, r2, r3);
            }
        }

        if (c + 1 < NPHASE) blend_store(c + 1);

        __syncthreads();
        // invariant: blend_store(c+1) wrote buf (c+1)&1, whose last readers
        // (mma(c-1)) all passed the sync at the end of iteration c-1.
    }

    // ---- 4. epilogue: bias + store (this warp: co rows wid*16+grp, +8; all 64 pix) ----
    {
        const int r0 = wid * 16 + grp;
        const int r1 = r0 + 8;
        const float bv0 = bias[r0];
        const float bv1 = bias[r1];
        float* o0 = out + ((size_t)(b * COUT + r0)) * HW + ho * 64 + 2 * t4;
        float* o1 = out + ((size_t)(b * COUT + r1)) * HW + ho * 64 + 2 * t4;
        #pragma unroll
        for (int nt = 0; nt < 8; nt++) {
            *(float2*)(o0 + nt * 8) = make_float2(acc[nt][0] + bv0, acc[nt][1] + bv0);
            *(float2*)(o1 + nt * 8) = make_float2(acc[nt][2] + bv1, acc[nt][3] + bv1);
        }
    }
}

// ---------------- launch ----------------
extern "C" void kernel_launch(void* const* d_in, const int* in_sizes, int n_in,
                              void* d_out, int out_size)
{
    const float* x      = (const float*)d_in[0];
    const float* offset = (const float*)d_in[1];
    const float* weight = (const float*)d_in[2];
    const float* bias   = (const float*)d_in[3];
    float* out = (float*)d_out;

    cudaFuncSetAttribute(deform_conv_mma_kernel,
                         cudaFuncAttributeMaxDynamicSharedMemorySize, SMEM_TOTAL);

    prep_all_kernel<<<2048 + 72, 256>>>(x, weight);
    deform_conv_mma_kernel<<<BB * 64, 256, SMEM_TOTAL>>>(offset, bias, out);
}

// round 11
// speedup vs baseline: 1.4075x; 1.4075x over previous
#include <cuda_runtime.h>
#include <cuda_fp16.h>
#include <cstdint>

// ---------------- problem constants ----------------
#define BB    8
#define CINC  128
#define COUT  128
#define HH    64
#define WW    64
#define HW    4096
#define KK    9
#define NPHASE 9       // K = 1152 = 9 phases of 128 (phase == tap)
#define NPIX  128      // pixels per CTA (2 output rows)
#define KPADH 136      // padded row length in halves (272B rows; (i*272)%128 covers all phases -> LDSM conflict-free)

// ---------------- dynamic smem layout (bytes) ----------------
#define OFF_IDX  0                         // ushort4[9*128] = 9216
#define OFF_WGT  9216                      // uint4[9*128]   = 18432 -> 27648 (half2-broadcast weights)
#define VTILE_BYTES (NPIX * KPADH * 2)     // 34816
#define OFF_V0   27648
#define OFF_V1   (OFF_V0 + VTILE_BYTES)    // 62464
#define SMEM_TOTAL (OFF_V1 + VTILE_BYTES)  // 97280

// weights pre-permuted into m16n8k16 fp16 A-fragment order:
// g_wfh[(kstep16_global*8 + mblock)*32 + lane], kstep16_global = tap*8 + cin16
__device__ uint4 g_wfh[72 * 8 * 32];
// NHWC-tiled x in fp16: g_xh[b][cinhalf(2)][yx][cin64]  (8 MB)
__device__ __half g_xh[BB * 2 * HW * 64];

__device__ __forceinline__ void mma_f16(float* d, const uint4 a, uint32_t b0, uint32_t b1) {
    asm volatile(
        "mma.sync.aligned.m16n8k16.row.col.f32.f16.f16.f32 "
        "{%0,%1,%2,%3}, {%4,%5,%6,%7}, {%8,%9}, {%0,%1,%2,%3};"
        : "+f"(d[0]), "+f"(d[1]), "+f"(d[2]), "+f"(d[3])
        : "r"(a.x), "r"(a.y), "r"(a.z), "r"(a.w), "r"(b0), "r"(b1));
}

__device__ __forceinline__ uint32_t smem_u32(const void* p) {
    uint32_t a;
    asm("{ .reg .u64 t; cvta.to.shared.u64 t, %1; cvt.u32.u64 %0, t; }" : "=r"(a) : "l"(p));
    return a;
}

// ---------------- merged prep: x transpose (blocks 0..2047) + weight permute (2048..2119) ----
__global__ void prep_all_kernel(const float* __restrict__ x,
                                const float* __restrict__ weight) {
    __shared__ float ts[32][65];
    const int bid = blockIdx.x;
    const int tid = threadIdx.x;

    if (bid < 2048) {
        // x transpose: NCHW f32 -> [b][cinhalf][yx][cin64] fp16
        const int yxt = bid & 63;
        const int blk = (bid >> 6) & 3;        // cin32 block 0..3
        const int b   = bid >> 8;
        const int yx0 = yxt * 64;

        const int yxl = tid & 63, cl = tid >> 6;
        const float* src = x + (((size_t)(b * CINC + blk * 32)) << 12) + yx0 + yxl;
        #pragma unroll
        for (int i = 0; i < 8; i++) {
            const int c = cl + i * 4;
            ts[c][yxl] = src[(size_t)c << 12];
        }
        __syncthreads();

        __half* dst = g_xh + ((((size_t)(b * 2 + (blk >> 1)) << 12) + yx0) << 6)
                    + ((blk & 1) << 5);
        const int c2 = tid & 31, yq = tid >> 5;
        #pragma unroll
        for (int i = 0; i < 8; i++) {
            const int yx = yq + i * 8;
            dst[(size_t)yx * 64 + c2] = __float2half(ts[c2][yx]);
        }
    } else {
        // weight prep: fp16 round + A-fragment permutation (18432 fragments)
        const int t = (bid - 2048) * 256 + tid;
        const int lane = t & 31;
        const int mb   = (t >> 5) & 7;
        const int ks   = (t >> 8) & 1;
        const int c    = t >> 9;                     // 32-k chunk id 0..35
        const int grp = lane >> 2, t4 = lane & 3;
        const int tap = c >> 2;
        const int cb  = ((c & 3) << 5) + ks * 16;    // cin base of this k16 step
        const int kA  = cb + t4 * 2;
        const int kB  = kA + 8;
        const int co0 = mb * 16 + grp;
        const int co1 = co0 + 8;
        #define WF(co, cin) __float2half_rn(weight[((co) * CINC + (cin)) * KK + tap])
        __half2 a0 = __halves2half2(WF(co0, kA), WF(co0, kA + 1));
        __half2 a1 = __halves2half2(WF(co1, kA), WF(co1, kA + 1));
        __half2 a2 = __halves2half2(WF(co0, kB), WF(co0, kB + 1));
        __half2 a3 = __halves2half2(WF(co1, kB), WF(co1, kB + 1));
        #undef WF
        uint4 u;
        u.x = *(uint32_t*)&a0; u.y = *(uint32_t*)&a1;
        u.z = *(uint32_t*)&a2; u.w = *(uint32_t*)&a3;
        g_wfh[t] = u;   // t == ((tap*8 + cin16)*8 + mb)*32 + lane by construction
    }
}

// ---------------- main kernel ----------------
__global__ __launch_bounds__(256, 2)
void deform_conv_mma_kernel(const float* __restrict__ offs,
                            const float* __restrict__ bias,
                            float* __restrict__ out)
{
    extern __shared__ char smem[];
    ushort4* sIdx = (ushort4*)(smem + OFF_IDX);
    uint4*   sWgt = (uint4*)(smem + OFF_WGT);   // 4x half2-broadcast bilinear weights
    const uint32_t sb = smem_u32(smem);

    const int tid  = threadIdx.x;
    const int wid  = tid >> 5;
    const int lane = tid & 31;

    const int b   = blockIdx.x >> 5;      // 32 CTAs per image
    const int rp  = blockIdx.x & 31;      // row-pair index
    const int ho0 = rp * 2;

    // ---- 1. sampling tables: 9 taps x 128 pix ----
    for (int e = tid; e < KK * NPIX; e += 256) {
        const int t  = e >> 7;
        const int pp = e & 127;
        const int ho = ho0 + (pp >> 6);
        const int wo = pp & 63;
        const int kh = t / 3;
        const int kw = t - kh * 3;
        const float* ob = offs + (((size_t)b * (2 * KK) + 2 * t) * HH + ho) * WW + wo;
        const float dy = ob[0];
        const float dx = ob[HW];
        const float py = (float)(ho - 1 + kh) + dy;
        const float px = (float)(wo - 1 + kw) + dx;
        const float y0f = floorf(py), x0f = floorf(px);
        const float ly = py - y0f, lx = px - x0f;
        const int y0 = (int)y0f, x0 = (int)x0f;
        const float wy0 = (y0 >= 0     && y0 < HH)     ? (1.0f - ly) : 0.0f;
        const float wy1 = (y0 + 1 >= 0 && y0 + 1 < HH) ? ly          : 0.0f;
        const float wx0 = (x0 >= 0     && x0 < WW)     ? (1.0f - lx) : 0.0f;
        const float wx1 = (x0 + 1 >= 0 && x0 + 1 < WW) ? lx          : 0.0f;
        const int cy0 = min(max(y0, 0), HH - 1), cy1 = min(max(y0 + 1, 0), HH - 1);
        const int cx0 = min(max(x0, 0), WW - 1), cx1 = min(max(x0 + 1, 0), WW - 1);
        sIdx[e] = make_ushort4((unsigned short)(cy0 * WW + cx0),
                               (unsigned short)(cy0 * WW + cx1),
                               (unsigned short)(cy1 * WW + cx0),
                               (unsigned short)(cy1 * WW + cx1));
        const __half2 h0 = __float2half2_rn(wy0 * wx0);
        const __half2 h1 = __float2half2_rn(wy0 * wx1);
        const __half2 h2 = __float2half2_rn(wy1 * wx0);
        const __half2 h3 = __float2half2_rn(wy1 * wx1);
        uint4 wq;
        wq.x = *(const uint32_t*)&h0; wq.y = *(const uint32_t*)&h1;
        wq.z = *(const uint32_t*)&h2; wq.w = *(const uint32_t*)&h3;
        sWgt[e] = wq;
    }
    __syncthreads();

    // ---- 2. GEMM setup ----
    const int pixg  = tid >> 3;           // pixel group 0..31
    const int lane8 = tid & 7;            // cin octet within 64 (8 halves = 16B)
    const int m0    = (wid & 3) << 5;     // warp cout base
    const int mb0   = (wid & 3) << 1;     // warp m-block base (16-row blocks)
    const int n0    = (wid >> 2) << 6;    // warp pixel base (64 wide)
    const int grp   = lane >> 2;
    const int t4    = lane & 3;

    // ldmatrix lane address components
    const int lm_pix = (lane & 7) + ((lane >> 4) << 3);  // 0..15
    const int lm_k   = ((lane >> 3) & 1) * 8;            // 0 or 8

    float acc[2][8][4];
    #pragma unroll
    for (int mt = 0; mt < 2; mt++)
        #pragma unroll
        for (int nt = 0; nt < 8; nt++)
            #pragma unroll
            for (int q = 0; q < 4; q++) acc[mt][nt][q] = 0.0f;

    // ---- 3. phase loop: 9 phases of K=128, double-buffered v, ONE sync per phase ----
    for (int c = 0; c < NPHASE; c++) {
        const int buf = c & 1;
        char* vb = smem + OFF_V0 + buf * VTILE_BYTES;
        const uint32_t vb32 = sb + OFF_V0 + buf * VTILE_BYTES;

        // bilinear gather: 8 lanes per pixel, ONE 128B line per (pixel, corner, cinhalf)
        #pragma unroll
        for (int pass = 0; pass < 4; pass++) {
            const int pix = pass * 32 + pixg;
            const int e   = c * 128 + pix;
            const ushort4 q = sIdx[e];
            const uint4   wq = sWgt[e];
            const __half2 w0 = *(const __half2*)&wq.x;
            const __half2 w1 = *(const __half2*)&wq.y;
            const __half2 w2 = *(const __half2*)&wq.z;
            const __half2 w3 = *(const __half2*)&wq.w;
            #pragma unroll
            for (int half64 = 0; half64 < 2; half64++) {
                const __half* pl = g_xh + ((size_t)(b * 2 + half64) << 18);
                const uint4 u0 = __ldg((const uint4*)(pl + (size_t)q.x * 64) + lane8);
                const uint4 u1 = __ldg((const uint4*)(pl + (size_t)q.y * 64) + lane8);
                const uint4 u2 = __ldg((const uint4*)(pl + (size_t)q.z * 64) + lane8);
                const uint4 u3 = __ldg((const uint4*)(pl + (size_t)q.w * 64) + lane8);
                const uint32_t* p0 = (const uint32_t*)&u0;
                const uint32_t* p1 = (const uint32_t*)&u1;
                const uint32_t* p2 = (const uint32_t*)&u2;
                const uint32_t* p3 = (const uint32_t*)&u3;
                uint4 st;
                uint32_t* s = (uint32_t*)&st;
                #pragma unroll
                for (int j = 0; j < 4; j++) {
                    __half2 r = __hmul2(w0, *(const __half2*)&p0[j]);
                    r = __hfma2(w1, *(const __half2*)&p1[j], r);
                    r = __hfma2(w2, *(const __half2*)&p2[j], r);
                    r = __hfma2(w3, *(const __half2*)&p3[j], r);
                    s[j] = *(const uint32_t*)&r;
                }
                *(uint4*)(vb + pix * (KPADH * 2) + (half64 * 64 + lane8 * 8) * 2) = st;
            }
        }

        __syncthreads();

        // mma: per warp 32co x 64pix; 8 ksteps of k16; B via ldmatrix.x4
        #pragma unroll
        for (int ks = 0; ks < 8; ks++) {
            const int g = c * 8 + ks;        // global k16 step 0..71
            const uint4 A0 = __ldg(&g_wfh[(g * 8 + mb0    ) * 32 + lane]);
            const uint4 A1 = __ldg(&g_wfh[(g * 8 + mb0 + 1) * 32 + lane]);
            #pragma unroll
            for (int p = 0; p < 4; p++) {
                const uint32_t addr = vb32
                    + (uint32_t)(n0 + p * 16 + lm_pix) * (KPADH * 2)
                    + (uint32_t)(ks * 16 + lm_k) * 2;
                uint32_t r0, r1, r2, r3;
                asm volatile(
                    "ldmatrix.sync.aligned.m8n8.x4.shared.b16 {%0,%1,%2,%3}, [%4];"
                    : "=r"(r0), "=r"(r1), "=r"(r2), "=r"(r3) : "r"(addr));
                mma_f16(acc[0][p * 2],     A0, r0, r1);
                mma_f16(acc[1][p * 2],     A1, r0, r1);
                mma_f16(acc[0][p * 2 + 1], A0, r2, r3);
                mma_f16(acc[1][p * 2 + 1], A1, r2, r3);
            }
        }
        // no trailing sync: gather(c+2) only happens after sync(c+1), and every
        // warp's mma(c) precedes sync(c+1) in program order.
    }

    // ---- 4. epilogue: bias + store ----
    #pragma unroll
    for (int mt = 0; mt < 2; mt++) {
        const int r0 = m0 + mt * 16 + grp;
        const int r1 = r0 + 8;
        const float bv0 = bias[r0];
        const float bv1 = bias[r1];
        float* o0 = out + ((size_t)(b * COUT + r0)) * HW + rp * 128 + n0 + 2 * t4;
        float* o1 = out + ((size_t)(b * COUT + r1)) * HW + rp * 128 + n0 + 2 * t4;
        #pragma unroll
        for (int nt = 0; nt < 8; nt++) {
            *(float2*)(o0 + nt * 8) = make_float2(acc[mt][nt][0] + bv0, acc[mt][nt][1] + bv0);
            *(float2*)(o1 + nt * 8) = make_float2(acc[mt][nt][2] + bv1, acc[mt][nt][3] + bv1);
        }
    }
}

// ---------------- launch ----------------
extern "C" void kernel_launch(void* const* d_in, const int* in_sizes, int n_in,
                              void* d_out, int out_size)
{
    const float* x      = (const float*)d_in[0];
    const float* offset = (const float*)d_in[1];
    const float* weight = (const float*)d_in[2];
    const float* bias   = (const float*)d_in[3];
    float* out = (float*)d_out;

    cudaFuncSetAttribute(deform_conv_mma_kernel,
                         cudaFuncAttributeMaxDynamicSharedMemorySize, SMEM_TOTAL);

    prep_all_kernel<<<2048 + 72, 256>>>(x, weight);
    deform_conv_mma_kernel<<<BB * 32, 256, SMEM_TOTAL>>>(offset, bias, out);
}

// round 12
// speedup vs baseline: 1.4462x; 1.0276x over previous
#include <cuda_runtime.h>
#include <cuda_fp16.h>
#include <cstdint>

// ---------------- problem constants ----------------
#define BB    8
#define CINC  128
#define COUT  128
#define HH    64
#define WW    64
#define HW    4096
#define KK    9
#define NPHASE 9       // K = 1152 = 9 phases of 128 (phase == tap)
#define NPIX  64       // pixels per CTA (1 output row)
#define KPADH 136      // padded row length in halves (272B rows -> LDSM/STS conflict-free)

// ---------------- dynamic smem layout (bytes) ----------------
#define OFF_IDX  0                         // ushort4[9*64] = 4608
#define OFF_WGT  4608                      // uint4[9*64]   = 9216 -> 13824 (half2-broadcast weights)
#define VTILE_BYTES (NPIX * KPADH * 2)     // 17408
#define OFF_V0   13824
#define OFF_V1   (OFF_V0 + VTILE_BYTES)    // 31232
#define SMEM_TOTAL (OFF_V1 + VTILE_BYTES)  // 48640

// weights pre-permuted into m16n8k16 fp16 A-fragment order:
// g_wfh[(kstep16_global*8 + mblock)*32 + lane], kstep16_global = tap*8 + cin16
__device__ uint4 g_wfh[72 * 8 * 32];
// NHWC-tiled x in fp16: g_xh[b][cinhalf(2)][yx][cin64]  (8 MB)
__device__ __half g_xh[BB * 2 * HW * 64];

__device__ __forceinline__ void mma_f16(float* d, const uint4 a, uint32_t b0, uint32_t b1) {
    asm volatile(
        "mma.sync.aligned.m16n8k16.row.col.f32.f16.f16.f32 "
        "{%0,%1,%2,%3}, {%4,%5,%6,%7}, {%8,%9}, {%0,%1,%2,%3};"
        : "+f"(d[0]), "+f"(d[1]), "+f"(d[2]), "+f"(d[3])
        : "r"(a.x), "r"(a.y), "r"(a.z), "r"(a.w), "r"(b0), "r"(b1));
}

__device__ __forceinline__ uint32_t smem_u32(const void* p) {
    uint32_t a;
    asm("{ .reg .u64 t; cvta.to.shared.u64 t, %1; cvt.u32.u64 %0, t; }" : "=r"(a) : "l"(p));
    return a;
}

// ---------------- merged prep: x transpose (blocks 0..2047) + weight permute (2048..2119) ----
__global__ void prep_all_kernel(const float* __restrict__ x,
                                const float* __restrict__ weight) {
    __shared__ float ts[32][65];
    const int bid = blockIdx.x;
    const int tid = threadIdx.x;

    if (bid < 2048) {
        // x transpose: NCHW f32 -> [b][cinhalf][yx][cin64] fp16
        const int yxt = bid & 63;
        const int blk = (bid >> 6) & 3;        // cin32 block 0..3
        const int b   = bid >> 8;
        const int yx0 = yxt * 64;

        const int yxl = tid & 63, cl = tid >> 6;
        const float* src = x + (((size_t)(b * CINC + blk * 32)) << 12) + yx0 + yxl;
        #pragma unroll
        for (int i = 0; i < 8; i++) {
            const int c = cl + i * 4;
            ts[c][yxl] = src[(size_t)c << 12];
        }
        __syncthreads();

        __half* dst = g_xh + ((((size_t)(b * 2 + (blk >> 1)) << 12) + yx0) << 6)
                    + ((blk & 1) << 5);
        const int c2 = tid & 31, yq = tid >> 5;
        #pragma unroll
        for (int i = 0; i < 8; i++) {
            const int yx = yq + i * 8;
            dst[(size_t)yx * 64 + c2] = __float2half(ts[c2][yx]);
        }
    } else {
        // weight prep: fp16 round + A-fragment permutation (18432 fragments)
        const int t = (bid - 2048) * 256 + tid;
        const int lane = t & 31;
        const int mb   = (t >> 5) & 7;
        const int ks   = (t >> 8) & 1;
        const int c    = t >> 9;                     // 32-k chunk id 0..35
        const int grp = lane >> 2, t4 = lane & 3;
        const int tap = c >> 2;
        const int cb  = ((c & 3) << 5) + ks * 16;    // cin base of this k16 step
        const int kA  = cb + t4 * 2;
        const int kB  = kA + 8;
        const int co0 = mb * 16 + grp;
        const int co1 = co0 + 8;
        #define WF(co, cin) __float2half_rn(weight[((co) * CINC + (cin)) * KK + tap])
        __half2 a0 = __halves2half2(WF(co0, kA), WF(co0, kA + 1));
        __half2 a1 = __halves2half2(WF(co1, kA), WF(co1, kA + 1));
        __half2 a2 = __halves2half2(WF(co0, kB), WF(co0, kB + 1));
        __half2 a3 = __halves2half2(WF(co1, kB), WF(co1, kB + 1));
        #undef WF
        uint4 u;
        u.x = *(uint32_t*)&a0; u.y = *(uint32_t*)&a1;
        u.z = *(uint32_t*)&a2; u.w = *(uint32_t*)&a3;
        g_wfh[t] = u;   // t == ((tap*8 + cin16)*8 + mb)*32 + lane by construction
    }
}

// ---------------- main kernel: 128 threads (4 warps), 4 CTAs/SM ----------------
__global__ __launch_bounds__(128, 4)
void deform_conv_mma_kernel(const float* __restrict__ offs,
                            const float* __restrict__ bias,
                            float* __restrict__ out)
{
    extern __shared__ char smem[];
    ushort4* sIdx = (ushort4*)(smem + OFF_IDX);
    uint4*   sWgt = (uint4*)(smem + OFF_WGT);   // 4x half2-broadcast bilinear weights
    const uint32_t sb = smem_u32(smem);

    const int tid  = threadIdx.x;
    const int wid  = tid >> 5;
    const int lane = tid & 31;

    const int b  = blockIdx.x >> 6;       // 64 CTAs per image (1 row each)
    const int ho = blockIdx.x & 63;       // output row

    // ---- 1. sampling tables: 9 taps x 64 pix ----
    for (int e = tid; e < KK * NPIX; e += 128) {
        const int t  = e >> 6;
        const int wo = e & 63;
        const int kh = t / 3;
        const int kw = t - kh * 3;
        const float* ob = offs + (((size_t)b * (2 * KK) + 2 * t) * HH + ho) * WW + wo;
        const float dy = ob[0];
        const float dx = ob[HW];
        const float py = (float)(ho - 1 + kh) + dy;
        const float px = (float)(wo - 1 + kw) + dx;
        const float y0f = floorf(py), x0f = floorf(px);
        const float ly = py - y0f, lx = px - x0f;
        const int y0 = (int)y0f, x0 = (int)x0f;
        const float wy0 = (y0 >= 0     && y0 < HH)     ? (1.0f - ly) : 0.0f;
        const float wy1 = (y0 + 1 >= 0 && y0 + 1 < HH) ? ly          : 0.0f;
        const float wx0 = (x0 >= 0     && x0 < WW)     ? (1.0f - lx) : 0.0f;
        const float wx1 = (x0 + 1 >= 0 && x0 + 1 < WW) ? lx          : 0.0f;
        const int cy0 = min(max(y0, 0), HH - 1), cy1 = min(max(y0 + 1, 0), HH - 1);
        const int cx0 = min(max(x0, 0), WW - 1), cx1 = min(max(x0 + 1, 0), WW - 1);
        sIdx[e] = make_ushort4((unsigned short)(cy0 * WW + cx0),
                               (unsigned short)(cy0 * WW + cx1),
                               (unsigned short)(cy1 * WW + cx0),
                               (unsigned short)(cy1 * WW + cx1));
        const __half2 h0 = __float2half2_rn(wy0 * wx0);
        const __half2 h1 = __float2half2_rn(wy0 * wx1);
        const __half2 h2 = __float2half2_rn(wy1 * wx0);
        const __half2 h3 = __float2half2_rn(wy1 * wx1);
        uint4 wq;
        wq.x = *(const uint32_t*)&h0; wq.y = *(const uint32_t*)&h1;
        wq.z = *(const uint32_t*)&h2; wq.w = *(const uint32_t*)&h3;
        sWgt[e] = wq;
    }
    __syncthreads();

    // ---- 2. GEMM setup ----
    const int pixg  = tid >> 3;           // pixel group 0..15
    const int lane8 = tid & 7;            // cin octet within 64 (8 halves = 16B)
    const int m0    = wid << 5;           // warp cout base (32 wide)
    const int mb0   = wid << 1;           // warp m-block base (16-row blocks)
    const int grp   = lane >> 2;
    const int t4    = lane & 3;

    // ldmatrix lane address components
    const int lm_pix = (lane & 7) + ((lane >> 4) << 3);  // 0..15
    const int lm_k   = ((lane >> 3) & 1) * 8;            // 0 or 8

    float acc[2][8][4];
    #pragma unroll
    for (int mt = 0; mt < 2; mt++)
        #pragma unroll
        for (int nt = 0; nt < 8; nt++)
            #pragma unroll
            for (int q = 0; q < 4; q++) acc[mt][nt][q] = 0.0f;

    // ---- 3. phase loop: 9 phases of K=128, double-buffered v, ONE sync per phase ----
    for (int c = 0; c < NPHASE; c++) {
        const int buf = c & 1;
        char* vb = smem + OFF_V0 + buf * VTILE_BYTES;
        const uint32_t vb32 = sb + OFF_V0 + buf * VTILE_BYTES;

        // bilinear gather: 8 lanes per pixel, ONE 128B line per (pixel, corner, cinhalf)
        #pragma unroll
        for (int pass = 0; pass < 4; pass++) {
            const int pix = pass * 16 + pixg;
            const int e   = c * 64 + pix;
            const ushort4 q = sIdx[e];
            const uint4   wq = sWgt[e];
            const __half2 w0 = *(const __half2*)&wq.x;
            const __half2 w1 = *(const __half2*)&wq.y;
            const __half2 w2 = *(const __half2*)&wq.z;
            const __half2 w3 = *(const __half2*)&wq.w;
            #pragma unroll
            for (int half64 = 0; half64 < 2; half64++) {
                const __half* pl = g_xh + ((size_t)(b * 2 + half64) << 18);
                const uint4 u0 = __ldg((const uint4*)(pl + (size_t)q.x * 64) + lane8);
                const uint4 u1 = __ldg((const uint4*)(pl + (size_t)q.y * 64) + lane8);
                const uint4 u2 = __ldg((const uint4*)(pl + (size_t)q.z * 64) + lane8);
                const uint4 u3 = __ldg((const uint4*)(pl + (size_t)q.w * 64) + lane8);
                const uint32_t* p0 = (const uint32_t*)&u0;
                const uint32_t* p1 = (const uint32_t*)&u1;
                const uint32_t* p2 = (const uint32_t*)&u2;
                const uint32_t* p3 = (const uint32_t*)&u3;
                uint4 st;
                uint32_t* s = (uint32_t*)&st;
                #pragma unroll
                for (int j = 0; j < 4; j++) {
                    __half2 r = __hmul2(w0, *(const __half2*)&p0[j]);
                    r = __hfma2(w1, *(const __half2*)&p1[j], r);
                    r = __hfma2(w2, *(const __half2*)&p2[j], r);
                    r = __hfma2(w3, *(const __half2*)&p3[j], r);
                    s[j] = *(const uint32_t*)&r;
                }
                *(uint4*)(vb + pix * (KPADH * 2) + (half64 * 64 + lane8 * 8) * 2) = st;
            }
        }

        __syncthreads();

        // mma: per warp 32co x 64pix; 8 ksteps of k16; B via ldmatrix.x4
        #pragma unroll
        for (int ks = 0; ks < 8; ks++) {
            const int g = c * 8 + ks;        // global k16 step 0..71
            const uint4 A0 = __ldg(&g_wfh[(g * 8 + mb0    ) * 32 + lane]);
            const uint4 A1 = __ldg(&g_wfh[(g * 8 + mb0 + 1) * 32 + lane]);
            #pragma unroll
            for (int p = 0; p < 4; p++) {
                const uint32_t addr = vb32
                    + (uint32_t)(p * 16 + lm_pix) * (KPADH * 2)
                    + (uint32_t)(ks * 16 + lm_k) * 2;
                uint32_t r0, r1, r2, r3;
                asm volatile(
                    "ldmatrix.sync.aligned.m8n8.x4.shared.b16 {%0,%1,%2,%3}, [%4];"
                    : "=r"(r0), "=r"(r1), "=r"(r2), "=r"(r3) : "r"(addr));
                mma_f16(acc[0][p * 2],     A0, r0, r1);
                mma_f16(acc[1][p * 2],     A1, r0, r1);
                mma_f16(acc[0][p * 2 + 1], A0, r2, r3);
                mma_f16(acc[1][p * 2 + 1], A1, r2, r3);
            }
        }
        // no trailing sync: gather(c+2) only happens after sync(c+1), and every
        // warp's mma(c) precedes sync(c+1) in program order.
    }

    // ---- 4. epilogue: bias + store ----
    #pragma unroll
    for (int mt = 0; mt < 2; mt++) {
        const int r0 = m0 + mt * 16 + grp;
        const int r1 = r0 + 8;
        const float bv0 = bias[r0];
        const float bv1 = bias[r1];
        float* o0 = out + ((size_t)(b * COUT + r0)) * HW + ho * WW + 2 * t4;
        float* o1 = out + ((size_t)(b * COUT + r1)) * HW + ho * WW + 2 * t4;
        #pragma unroll
        for (int nt = 0; nt < 8; nt++) {
            *(float2*)(o0 + nt * 8) = make_float2(acc[mt][nt][0] + bv0, acc[mt][nt][1] + bv0);
            *(float2*)(o1 + nt * 8) = make_float2(acc[mt][nt][2] + bv1, acc[mt][nt][3] + bv1);
        }
    }
}

// ---------------- launch ----------------
extern "C" void kernel_launch(void* const* d_in, const int* in_sizes, int n_in,
                              void* d_out, int out_size)
{
    const float* x      = (const float*)d_in[0];
    const float* offset = (const float*)d_in[1];
    const float* weight = (const float*)d_in[2];
    const float* bias   = (const float*)d_in[3];
    float* out = (float*)d_out;

    cudaFuncSetAttribute(deform_conv_mma_kernel,
                         cudaFuncAttributeMaxDynamicSharedMemorySize, SMEM_TOTAL);

    prep_all_kernel<<<2048 + 72, 256>>>(x, weight);
    deform_conv_mma_kernel<<<BB * 64, 128, SMEM_TOTAL>>>(offset, bias, out);
}